// round 16
// baseline (speedup 1.0000x reference)
#include <cuda_runtime.h>
#include <cuda_fp16.h>
#include <cstdint>

// ---------------------------------------------------------------------------
// Problem constants
// ---------------------------------------------------------------------------
#define Bn     32
#define Nn     2048
#define PDn    2
#define LATn   128
#define Hn     256
#define STEPSn 5
#define DINn   131
#define NPTS   (Bn * Nn)         // 65536
#define PPC    64                // points per CTA (= GEMM M)
#define NCTA   (NPTS / PPC)      // 1024
#define KCH    64                // K-chunk
#define NCHUNK (Hn / KCH)        // 4
#define NTHREADS 256
#define NTILES (STEPSn * 2 * NCHUNK)   // 40 B-tiles over the whole kernel

// ---------------------------------------------------------------------------
// Device globals
// ---------------------------------------------------------------------------
// fp16 weights, chunk-major: [matrix(2: W2, M)][chunk(4)][j=256][kk=64]
__device__ __align__(16) __half g_W16[2 * NCHUNK * Hn * KCH];
__device__ __align__(16) float g_base[Bn * Hn];
__device__ __align__(16) float g_c0[Hn], g_c1[Hn], g_ct[Hn], g_csum[Hn];

// Batched tanh: 4 tanh sharing one reciprocal (5 MUFU instead of 8).
__device__ __forceinline__ void ftanh4(const float* u, float* h) {
    float e0 = __expf(2.0f * fminf(fmaxf(u[0], -9.f), 9.f));
    float e1 = __expf(2.0f * fminf(fmaxf(u[1], -9.f), 9.f));
    float e2 = __expf(2.0f * fminf(fmaxf(u[2], -9.f), 9.f));
    float e3 = __expf(2.0f * fminf(fmaxf(u[3], -9.f), 9.f));
    float d0 = e0 + 1.f, d1 = e1 + 1.f, d2 = e2 + 1.f, d3 = e3 + 1.f;
    float p01 = d0 * d1, p23 = d2 * d3;
    float r = __fdividef(1.0f, p01 * p23);
    float r01 = r * p23, r23 = r * p01;
    h[0] = fmaf(-2.0f, r01 * d1, 1.0f);
    h[1] = fmaf(-2.0f, r01 * d0, 1.0f);
    h[2] = fmaf(-2.0f, r23 * d3, 1.0f);
    h[3] = fmaf(-2.0f, r23 * d2, 1.0f);
}
__device__ __forceinline__ uint32_t smem_u32(const void* p) {
    uint32_t a;
    asm("{ .reg .u64 t; cvta.to.shared.u64 t, %1; cvt.u32.u64 %0, t; }"
        : "=r"(a) : "l"(p));
    return a;
}
__device__ __forceinline__ void ldsm4(uint32_t& r0, uint32_t& r1,
                                      uint32_t& r2, uint32_t& r3, uint32_t addr) {
    asm volatile("ldmatrix.sync.aligned.m8n8.x4.shared.b16 {%0,%1,%2,%3}, [%4];"
                 : "=r"(r0), "=r"(r1), "=r"(r2), "=r"(r3) : "r"(addr));
}
__device__ __forceinline__ void mma16816(float* d, const uint32_t* a,
                                         uint32_t b0, uint32_t b1) {
    asm volatile(
        "mma.sync.aligned.m16n8k16.row.col.f32.f16.f16.f32 "
        "{%0,%1,%2,%3},{%4,%5,%6,%7},{%8,%9},{%0,%1,%2,%3};"
        : "+f"(d[0]), "+f"(d[1]), "+f"(d[2]), "+f"(d[3])
        : "r"(a[0]), "r"(a[1]), "r"(a[2]), "r"(a[3]), "r"(b0), "r"(b1));
}
__device__ __forceinline__ void cp16(uint32_t dst, const void* src) {
    asm volatile("cp.async.cg.shared.global [%0], [%1], 16;"
                 :: "r"(dst), "l"(src));
}
#define CP_COMMIT() asm volatile("cp.async.commit_group;" ::: "memory")
#define CP_WAIT0()  asm volatile("cp.async.wait_group 0;" ::: "memory")

// ---------------------------------------------------------------------------
// Precompute 1: per-row W1 decomposition + per-batch base vectors
// ---------------------------------------------------------------------------
__global__ void precomp_aux(const float* __restrict__ W1,
                            const float* __restrict__ b1,
                            const float* __restrict__ z) {
    int k = threadIdx.x;
    int b = blockIdx.x;
    const float* row = W1 + k * DINn;
    float d = b1[k];
    const float* zb = z + b * LATn;
#pragma unroll 16
    for (int l = 0; l < LATn; ++l) d += row[3 + l] * zb[l];
    g_base[b * Hn + k] = d;
    if (b == 0) {
        float s = 0.f;
#pragma unroll 16
        for (int l = 0; l < LATn; ++l) s += row[3 + l];
        g_c0[k] = row[0]; g_c1[k] = row[1]; g_ct[k] = row[2]; g_csum[k] = s;
    }
}

// ---------------------------------------------------------------------------
// Precompute 2: W2 and fused divergence matrix M -> fp16, chunk-major
// ---------------------------------------------------------------------------
__global__ void precomp_w(const float* __restrict__ W1,
                          const float* __restrict__ W2,
                          const float* __restrict__ W3) {
    int j = blockIdx.x;   // 256
    int k = threadIdx.x;  // 256
    float w2 = W2[j * Hn + k];
    float mm = w2 * (W1[k * DINn] * W3[j] + W1[k * DINn + 1] * W3[Hn + j]);
    int chunk = k >> 6, kk = k & 63;
    int idx = chunk * (Hn * KCH) + j * KCH + kk;
    g_W16[idx] = __float2half_rn(w2);
    g_W16[NCHUNK * Hn * KCH + idx] = __float2half_rn(mm);
}

// ---------------------------------------------------------------------------
// SMEM layout (byte offsets) — sized for 2 CTAs/SM (~102 KB)
// ---------------------------------------------------------------------------
#define SM_C0    0
#define SM_C1    1024
#define SM_CT    2048
#define SM_CS    3072
#define SM_BASE  4096
#define SM_B2    5120
#define SM_W30   6144
#define SM_W31   7168
#define SM_X0    8192          // 64 f32
#define SM_X1    8448
#define SM_SS    8704
#define SM_PART  8960          // [3][4][64] f32 = 3072 -> 12032
#define SM_A     12032         // 2 bufs x (64 x 72 halfs = 9216) = 18432
#define SM_B     30464         // 2 bufs x (256 x 72 halfs = 36864) = 73728
#define SM_TOTAL 104192

#define ABUF_SZ  9216
#define BBUF_SZ  36864

// ---------------------------------------------------------------------------
// Main fused CNF kernel, 2 CTAs/SM (occupancy play):
// PPC=64, 8 warps (2M x 4N, 32x64 warp tiles), regs <= 128.
// pass0 = velocity GEMM (h), pass1 = divergence GEMM (g1, recomputed as
// pipeline filler into the same A ping-pong). g2 stash in registers.
// One CTA's barriers/epilogues hide under the sibling CTA's MMA.
// ---------------------------------------------------------------------------
__global__ void __launch_bounds__(NTHREADS, 2)
cnf_kernel(const float* __restrict__ x,
           const float* __restrict__ b2,
           const float* __restrict__ W3,
           const float* __restrict__ b3,
           const float* __restrict__ osc,
           float* __restrict__ out,
           int out_size) {
    extern __shared__ char smem[];
    float* sf = reinterpret_cast<float*>(smem);
    const uint32_t sb = smem_u32(smem);

    const int tid  = threadIdx.x;
    const int wid  = tid >> 5;
    const int lane = tid & 31;
    const int gp0  = blockIdx.x * PPC;
    const int bidx = gp0 >> 11;

    // constants -> smem
    sf[(SM_C0 >> 2) + tid]   = g_c0[tid];
    sf[(SM_C1 >> 2) + tid]   = g_c1[tid];
    sf[(SM_CT >> 2) + tid]   = g_ct[tid];
    sf[(SM_CS >> 2) + tid]   = g_csum[tid];
    sf[(SM_BASE >> 2) + tid] = g_base[bidx * Hn + tid];
    sf[(SM_B2 >> 2) + tid]   = b2[tid];
    sf[(SM_W30 >> 2) + tid]  = W3[tid];
    sf[(SM_W31 >> 2) + tid]  = W3[Hn + tid];
    if (tid < PPC) {
        int gp = gp0 + tid;
        sf[(SM_X0 >> 2) + tid] = x[gp * 2 + 0];
        sf[(SM_X1 >> 2) + tid] = x[gp * 2 + 1];
        sf[(SM_SS >> 2) + tid] = 0.f;
    }

// issue B-tile q into buffer (q&1): 2048 uint4 of data, 8 rounds x 256 thr
#define ISSUE_B(q) do {                                                    \
        int _q8 = (q) & 7;                                                 \
        int _img = (_q8 >= NCHUNK) ? 1 : 0;                                \
        int _ch  = (q) & 3;                                                \
        const __half* _src = g_W16 + (_img * NCHUNK + _ch) * (Hn * KCH);   \
        uint32_t _dst = sb + SM_B + (uint32_t)((q) & 1) * BBUF_SZ;         \
        _Pragma("unroll")                                                  \
        for (int _i = 0; _i < 8; ++_i) {                                   \
            int _idx = _i * NTHREADS + tid;                                \
            int _j = _idx >> 3, _kb = _idx & 7;                            \
            cp16(_dst + (uint32_t)_j * 144u + (uint32_t)_kb * 16u,         \
                 _src + _idx * 8);                                         \
        }                                                                  \
        CP_COMMIT();                                                       \
    } while (0)

    ISSUE_B(0);
    __syncthreads();

    const float scale = __ldg(osc);
    const float dt  = 1.0f / (float)STEPSn;
    const float b30 = __ldg(b3), b31 = __ldg(b3 + 1);

    // layer-1 mapping: 64 points x 4 k-quarters of 16
    const int p_mine = tid >> 2;
    const int kq     = tid & 3;
    // mma warp tiling: 2 (M) x 4 (N), 32x64 warp tiles
    const int warp_m = wid >> 2;
    const int warp_n = wid & 3;
    const int m0w = warp_m * 32;
    const int n0w = warp_n * 64;
    const int grp = lane >> 2, tig = lane & 3;
    const uint32_t aoff = (uint32_t)(lane & 15) * 144u + ((uint32_t)(lane >> 4) << 4);
    const uint32_t boff = ((uint32_t)((lane & 7) + ((lane >> 4) << 3))) * 144u
                        + (((uint32_t)(lane >> 3) & 1u) << 4);

    const float* c0s = sf + (SM_C0 >> 2);
    const float* c1s = sf + (SM_C1 >> 2);
    const float* cts = sf + (SM_CT >> 2);
    const float* css = sf + (SM_CS >> 2);
    const float* bas = sf + (SM_BASE >> 2);
    const float* b2s = sf + (SM_B2 >> 2);
    const float* w30s = sf + (SM_W30 >> 2);
    const float* w31s = sf + (SM_W31 >> 2);
    float* part = sf + (SM_PART >> 2);

    uint32_t g2a[2][8], g2b[2][8];   // layer-2 derivative stash (packed half2)

#pragma unroll 1
    for (int step = 0; step < STEPSn; ++step) {
        const float tcur = dt * (float)step;
        const float px0 = sf[(SM_X0 >> 2) + p_mine];
        const float px1 = sf[(SM_X1 >> 2) + p_mine];
        const float psv = sf[(SM_SS >> 2) + p_mine];

        // layer-1 k-slice for chunk c into A buf (c&1); want_g selects h vs g1
        auto layer1 = [&](int c, bool want_g) {
            const int kkb = kq * 16;
            const uint32_t aw = (uint32_t)(c & 1) * ABUF_SZ;
#pragma unroll
            for (int kk2 = 0; kk2 < 16; kk2 += 4) {
                int kk = kkb + kk2;
                int k = c * KCH + kk;
                float u[4], h[4];
#pragma unroll
                for (int t2 = 0; t2 < 4; ++t2) {
                    int kt = k + t2;
                    u[t2] = bas[kt] + tcur * cts[kt] + psv * css[kt]
                          + px0 * c0s[kt] + px1 * c1s[kt];
                }
                ftanh4(u, h);
                if (want_g) {
#pragma unroll
                    for (int t2 = 0; t2 < 4; ++t2) h[t2] = 1.f - h[t2] * h[t2];
                }
                uint32_t o = aw + (uint32_t)p_mine * 144u + (uint32_t)kk * 2u;
                *reinterpret_cast<__half2*>(smem + SM_A + o) =
                    __floats2half2_rn(h[0], h[1]);
                *reinterpret_cast<__half2*>(smem + SM_A + o + 4u) =
                    __floats2half2_rn(h[2], h[3]);
            }
        };

        float acc[2][8][4];

#pragma unroll 1
        for (int pass = 0; pass < 2; ++pass) {
#pragma unroll
            for (int mi = 0; mi < 2; ++mi)
#pragma unroll
                for (int ni = 0; ni < 8; ++ni)
#pragma unroll
                    for (int q = 0; q < 4; ++q) acc[mi][ni][q] = 0.f;

            layer1(0, pass != 0);
#pragma unroll 1
            for (int chunk = 0; chunk < NCHUNK; ++chunk) {
                const int q = step * 8 + pass * 4 + chunk;

                CP_WAIT0();          // B(q) landed
                __syncthreads();     // A(chunk) stores + B visible; prev reads done
                if (q + 1 < NTILES) ISSUE_B(q + 1);

                const uint32_t bb = sb + SM_B + (uint32_t)(q & 1) * BBUF_SZ;
                const uint32_t ab = sb + SM_A + (uint32_t)(chunk & 1) * ABUF_SZ;
#pragma unroll
                for (int ks = 0; ks < 4; ++ks) {
                    uint32_t a[2][4];
#pragma unroll
                    for (int mi = 0; mi < 2; ++mi) {
                        uint32_t ad = ab + (uint32_t)(m0w + mi * 16) * 144u
                                    + (uint32_t)ks * 32u + aoff;
                        ldsm4(a[mi][0], a[mi][1], a[mi][2], a[mi][3], ad);
                    }
#pragma unroll
                    for (int ng = 0; ng < 4; ++ng) {
                        uint32_t r0, r1, r2, r3;
                        uint32_t bd = bb + (uint32_t)(n0w + ng * 16) * 144u
                                    + (uint32_t)ks * 32u + boff;
                        ldsm4(r0, r1, r2, r3, bd);
#pragma unroll
                        for (int mi = 0; mi < 2; ++mi) {
                            mma16816(acc[mi][ng * 2],     a[mi], r0, r1);
                            mma16816(acc[mi][ng * 2 + 1], a[mi], r2, r3);
                        }
                    }
                }
                // layer-1 for chunk+1 into the OTHER A buffer (pipeline filler)
                if (chunk + 1 < NCHUNK) layer1(chunk + 1, pass != 0);
            }

            if (pass == 0) {
                // ---- epilogue 0: h2, v partials; g2 -> registers ----
                float v0p[4], v1p[4];
#pragma unroll
                for (int i = 0; i < 4; ++i) { v0p[i] = 0.f; v1p[i] = 0.f; }
#pragma unroll
                for (int mi = 0; mi < 2; ++mi) {
#pragma unroll
                    for (int ni = 0; ni < 8; ++ni) {
                        int j0 = n0w + ni * 8 + tig * 2;
                        float* c = acc[mi][ni];
                        float bj0 = b2s[j0], bj1 = b2s[j0 + 1];
                        float u[4] = {c[0] + bj0, c[1] + bj1, c[2] + bj0, c[3] + bj1};
                        float h[4];
                        ftanh4(u, h);
                        float w300 = w30s[j0], w301 = w30s[j0 + 1];
                        float w310 = w31s[j0], w311 = w31s[j0 + 1];
                        v0p[2*mi]   += w300 * h[0] + w301 * h[1];
                        v0p[2*mi+1] += w300 * h[2] + w301 * h[3];
                        v1p[2*mi]   += w310 * h[0] + w311 * h[1];
                        v1p[2*mi+1] += w310 * h[2] + w311 * h[3];
                        __half2 ga = __floats2half2_rn(1.f - h[0] * h[0], 1.f - h[1] * h[1]);
                        __half2 gb = __floats2half2_rn(1.f - h[2] * h[2], 1.f - h[3] * h[3]);
                        g2a[mi][ni] = *reinterpret_cast<uint32_t*>(&ga);
                        g2b[mi][ni] = *reinterpret_cast<uint32_t*>(&gb);
                    }
                }
#pragma unroll
                for (int i = 0; i < 4; ++i) {
                    v0p[i] += __shfl_xor_sync(0xffffffffu, v0p[i], 1);
                    v0p[i] += __shfl_xor_sync(0xffffffffu, v0p[i], 2);
                    v1p[i] += __shfl_xor_sync(0xffffffffu, v1p[i], 1);
                    v1p[i] += __shfl_xor_sync(0xffffffffu, v1p[i], 2);
                }
                if (tig == 0) {
#pragma unroll
                    for (int i = 0; i < 4; ++i) {
                        int p = m0w + (i >> 1) * 16 + grp + (i & 1) * 8;
                        part[0 * 256 + warp_n * 64 + p] = v0p[i];
                        part[1 * 256 + warp_n * 64 + p] = v1p[i];
                    }
                }
            } else {
                // ---- epilogue 1: dv partials from g2 registers ----
                float dvp[4];
#pragma unroll
                for (int i = 0; i < 4; ++i) dvp[i] = 0.f;
#pragma unroll
                for (int mi = 0; mi < 2; ++mi) {
#pragma unroll
                    for (int ni = 0; ni < 8; ++ni) {
                        float* c = acc[mi][ni];
                        float2 ga = __half22float2(
                            *reinterpret_cast<__half2*>(&g2a[mi][ni]));
                        float2 gb = __half22float2(
                            *reinterpret_cast<__half2*>(&g2b[mi][ni]));
                        dvp[2*mi]   += ga.x * c[0] + ga.y * c[1];
                        dvp[2*mi+1] += gb.x * c[2] + gb.y * c[3];
                    }
                }
#pragma unroll
                for (int i = 0; i < 4; ++i) {
                    dvp[i] += __shfl_xor_sync(0xffffffffu, dvp[i], 1);
                    dvp[i] += __shfl_xor_sync(0xffffffffu, dvp[i], 2);
                }
                if (tig == 0) {
#pragma unroll
                    for (int i = 0; i < 4; ++i) {
                        int p = m0w + (i >> 1) * 16 + grp + (i & 1) * 8;
                        part[2 * 256 + warp_n * 64 + p] = dvp[i];
                    }
                }
            }
        }
        __syncthreads();

        // ---- state update ----
        if (tid < PPC) {
            float v0 = b30, v1 = b31, dv = 0.f;
#pragma unroll
            for (int wn = 0; wn < 4; ++wn) {
                v0 += part[0 * 256 + wn * 64 + tid];
                v1 += part[1 * 256 + wn * 64 + tid];
                dv += part[2 * 256 + wn * 64 + tid];
            }
            sf[(SM_X0 >> 2) + tid] += v0 * scale * dt;
            sf[(SM_X1 >> 2) + tid] += v1 * scale * dt;
            sf[(SM_SS >> 2) + tid] += dv * scale * dt;
        }
        __syncthreads();
    }

    if (tid < PPC) {
        int gp = gp0 + tid;
        out[gp * 2 + 0] = sf[(SM_X0 >> 2) + tid];
        out[gp * 2 + 1] = sf[(SM_X1 >> 2) + tid];
        if (out_size >= NPTS * PDn + NPTS)
            out[NPTS * PDn + gp] = sf[(SM_SS >> 2) + tid];
    }
#undef ISSUE_B
}

// ---------------------------------------------------------------------------
// kernel_launch
// Inputs (metadata order): x, z, W1, b1, W2, b2, W3, b3, out_scale
// ---------------------------------------------------------------------------
extern "C" void kernel_launch(void* const* d_in, const int* in_sizes, int n_in,
                              void* d_out, int out_size) {
    const float* x   = (const float*)d_in[0];
    const float* z   = (const float*)d_in[1];
    const float* W1  = (const float*)d_in[2];
    const float* b1  = (const float*)d_in[3];
    const float* W2  = (const float*)d_in[4];
    const float* b2  = (const float*)d_in[5];
    const float* W3  = (const float*)d_in[6];
    const float* b3  = (const float*)d_in[7];
    const float* osc = (const float*)d_in[8];
    float* out = (float*)d_out;

    precomp_aux<<<Bn, 256>>>(W1, b1, z);
    precomp_w<<<256, 256>>>(W1, W2, W3);

    cudaFuncSetAttribute(cnf_kernel, cudaFuncAttributeMaxDynamicSharedMemorySize,
                         SM_TOTAL);
    cnf_kernel<<<NCTA, NTHREADS, SM_TOTAL>>>(x, b2, W3, b3, osc, out, out_size);
}

// round 17
// speedup vs baseline: 1.2330x; 1.2330x over previous
#include <cuda_runtime.h>
#include <cuda_fp16.h>
#include <cstdint>

// ---------------------------------------------------------------------------
// Problem constants
// ---------------------------------------------------------------------------
#define Bn     32
#define Nn     2048
#define PDn    2
#define LATn   128
#define Hn     256
#define STEPSn 5
#define DINn   131
#define NPTS   (Bn * Nn)         // 65536
#define KCH    64                // K-chunk
#define NCHUNK (Hn / KCH)        // 4
#define NTHREADS 256
#define NTILES (STEPSn * 2 * NCHUNK)   // 40 B-tiles over the whole kernel

// Tail-wave split: 444 CTAs x 128 pts (3 exact waves) + 136 CTAs x 64 pts
#define NCTA1  444
#define PTS1   (NCTA1 * 128)     // 56832
#define NCTA2  136               // (65536-56832)/64

// ---------------------------------------------------------------------------
// Device globals
// ---------------------------------------------------------------------------
// fp16 weights, chunk-major: [matrix(2: W2, M)][chunk(4)][j=256][kk=64]
__device__ __align__(16) __half g_W16[2 * NCHUNK * Hn * KCH];
__device__ __align__(16) float g_base[Bn * Hn];
__device__ __align__(16) float g_c0[Hn], g_c1[Hn], g_ct[Hn], g_csum[Hn];

// Batched tanh: 4 tanh sharing one reciprocal (5 MUFU instead of 8).
__device__ __forceinline__ void ftanh4(const float* u, float* h) {
    float e0 = __expf(2.0f * fminf(fmaxf(u[0], -9.f), 9.f));
    float e1 = __expf(2.0f * fminf(fmaxf(u[1], -9.f), 9.f));
    float e2 = __expf(2.0f * fminf(fmaxf(u[2], -9.f), 9.f));
    float e3 = __expf(2.0f * fminf(fmaxf(u[3], -9.f), 9.f));
    float d0 = e0 + 1.f, d1 = e1 + 1.f, d2 = e2 + 1.f, d3 = e3 + 1.f;
    float p01 = d0 * d1, p23 = d2 * d3;
    float r = __fdividef(1.0f, p01 * p23);
    float r01 = r * p23, r23 = r * p01;
    h[0] = fmaf(-2.0f, r01 * d1, 1.0f);
    h[1] = fmaf(-2.0f, r01 * d0, 1.0f);
    h[2] = fmaf(-2.0f, r23 * d3, 1.0f);
    h[3] = fmaf(-2.0f, r23 * d2, 1.0f);
}
__device__ __forceinline__ uint32_t smem_u32(const void* p) {
    uint32_t a;
    asm("{ .reg .u64 t; cvta.to.shared.u64 t, %1; cvt.u32.u64 %0, t; }"
        : "=r"(a) : "l"(p));
    return a;
}
__device__ __forceinline__ void ldsm4(uint32_t& r0, uint32_t& r1,
                                      uint32_t& r2, uint32_t& r3, uint32_t addr) {
    asm volatile("ldmatrix.sync.aligned.m8n8.x4.shared.b16 {%0,%1,%2,%3}, [%4];"
                 : "=r"(r0), "=r"(r1), "=r"(r2), "=r"(r3) : "r"(addr));
}
__device__ __forceinline__ void mma16816(float* d, const uint32_t* a,
                                         uint32_t b0, uint32_t b1) {
    asm volatile(
        "mma.sync.aligned.m16n8k16.row.col.f32.f16.f16.f32 "
        "{%0,%1,%2,%3},{%4,%5,%6,%7},{%8,%9},{%0,%1,%2,%3};"
        : "+f"(d[0]), "+f"(d[1]), "+f"(d[2]), "+f"(d[3])
        : "r"(a[0]), "r"(a[1]), "r"(a[2]), "r"(a[3]), "r"(b0), "r"(b1));
}
__device__ __forceinline__ void cp16(uint32_t dst, const void* src) {
    asm volatile("cp.async.cg.shared.global [%0], [%1], 16;"
                 :: "r"(dst), "l"(src));
}
#define CP_COMMIT() asm volatile("cp.async.commit_group;" ::: "memory")
#define CP_WAIT0()  asm volatile("cp.async.wait_group 0;" ::: "memory")

// ---------------------------------------------------------------------------
// Precompute 1 (fast): one block per k (256 blocks), 128 threads (one per l),
// coalesced W1 reads, z staged in smem, shuffle reductions.
// ---------------------------------------------------------------------------
__global__ void precomp_aux(const float* __restrict__ W1,
                            const float* __restrict__ b1,
                            const float* __restrict__ z) {
    __shared__ float zs[Bn * LATn];   // 16 KB
    __shared__ float wred[4];
    const int k = blockIdx.x;
    const int l = threadIdx.x;        // 128 threads
    for (int i = l; i < Bn * LATn; i += 128) zs[i] = z[i];
    float w = W1[k * DINn + 3 + l];
    const int warp = l >> 5, lane = l & 31;
    __syncthreads();

    // csum + scalar coeffs
    float s = w;
#pragma unroll
    for (int o = 16; o; o >>= 1) s += __shfl_xor_sync(0xffffffffu, s, o);
    if (lane == 0) wred[warp] = s;
    __syncthreads();
    if (l == 0) {
        g_csum[k] = wred[0] + wred[1] + wred[2] + wred[3];
        g_c0[k] = W1[k * DINn];
        g_c1[k] = W1[k * DINn + 1];
        g_ct[k] = W1[k * DINn + 2];
    }
    float bk = b1[k];
#pragma unroll 1
    for (int b = 0; b < Bn; ++b) {
        float v = w * zs[b * LATn + l];
#pragma unroll
        for (int o = 16; o; o >>= 1) v += __shfl_xor_sync(0xffffffffu, v, o);
        __syncthreads();               // previous wred read complete
        if (lane == 0) wred[warp] = v;
        __syncthreads();
        if (l == 0) g_base[b * Hn + k] = bk + wred[0] + wred[1] + wred[2] + wred[3];
    }
}

// ---------------------------------------------------------------------------
// Precompute 2: W2 and fused divergence matrix M -> fp16, chunk-major
// ---------------------------------------------------------------------------
__global__ void precomp_w(const float* __restrict__ W1,
                          const float* __restrict__ W2,
                          const float* __restrict__ W3) {
    int j = blockIdx.x;   // 256
    int k = threadIdx.x;  // 256
    float w2 = W2[j * Hn + k];
    float mm = w2 * (W1[k * DINn] * W3[j] + W1[k * DINn + 1] * W3[Hn + j]);
    int chunk = k >> 6, kk = k & 63;
    int idx = chunk * (Hn * KCH) + j * KCH + kk;
    g_W16[idx] = __float2half_rn(w2);
    g_W16[NCHUNK * Hn * KCH + idx] = __float2half_rn(mm);
}

// ---------------------------------------------------------------------------
// Common SMEM offsets (constants region)
// ---------------------------------------------------------------------------
#define SM_C0    0
#define SM_C1    1024
#define SM_CT    2048
#define SM_CS    3072
#define SM_BASE  4096
#define SM_B2    5120
#define SM_W30   6144
#define SM_W31   7168
// per-template state/part/A/B/AG follow (see constexprs below)

// ---------------------------------------------------------------------------
// Main fused CNF kernel (templated on points-per-CTA).
// Structure = the 429us kernel: tanh once/step via ftanh4; pass0 velocity GEMM
// (h . W2) with A ping-pong + layer-1 pipelined; pass1 divergence GEMM
// (g1 full-width . M); g2 stash in registers; cp.async double-buffered B.
// ---------------------------------------------------------------------------
template <int PPCT>
__global__ void __launch_bounds__(NTHREADS, 1)
cnf_kernel(const float* __restrict__ x,
           const float* __restrict__ b2,
           const float* __restrict__ W3,
           const float* __restrict__ b3,
           const float* __restrict__ osc,
           float* __restrict__ out,
           int out_size, int pt_base) {
    constexpr int MI   = PPCT / 32;           // M-subtiles (16 rows) per warp
    constexpr int TPP  = NTHREADS / PPCT;     // threads per point (layer-1)
    constexpr int KPT  = KCH / TPP;           // k's per thread per chunk
    constexpr int C_X0 = 8192;
    constexpr int C_X1 = C_X0 + PPCT * 4;
    constexpr int C_SS = C_X1 + PPCT * 4;
    constexpr int C_PART = C_SS + PPCT * 4;   // [3][4][PPCT] f32
    constexpr int C_A  = (C_PART + 12 * PPCT * 4 + 127) & ~127;
    constexpr int ABUF = PPCT * 144;
    constexpr int C_B  = C_A + 2 * ABUF;
    constexpr int BBUF = 36864;
    constexpr int C_AG = C_B + 2 * BBUF;
    constexpr int AG_STRIDE = 528;

    extern __shared__ char smem[];
    float* sf = reinterpret_cast<float*>(smem);
    const uint32_t sb = smem_u32(smem);

    const int tid  = threadIdx.x;
    const int wid  = tid >> 5;
    const int lane = tid & 31;
    const int gp0  = pt_base + blockIdx.x * PPCT;
    const int bidx = gp0 >> 11;

    // constants -> smem
    sf[(SM_C0 >> 2) + tid]   = g_c0[tid];
    sf[(SM_C1 >> 2) + tid]   = g_c1[tid];
    sf[(SM_CT >> 2) + tid]   = g_ct[tid];
    sf[(SM_CS >> 2) + tid]   = g_csum[tid];
    sf[(SM_BASE >> 2) + tid] = g_base[bidx * Hn + tid];
    sf[(SM_B2 >> 2) + tid]   = b2[tid];
    sf[(SM_W30 >> 2) + tid]  = W3[tid];
    sf[(SM_W31 >> 2) + tid]  = W3[Hn + tid];
    if (tid < PPCT) {
        int gp = gp0 + tid;
        sf[(C_X0 >> 2) + tid] = x[gp * 2 + 0];
        sf[(C_X1 >> 2) + tid] = x[gp * 2 + 1];
        sf[(C_SS >> 2) + tid] = 0.f;
    }

    // issue B-tile q into buffer (q&1): 2048 uint4 of data, 8 rounds
    auto issue_b = [&](int q) {
        int q8 = q & 7;
        int img = (q8 >= NCHUNK) ? 1 : 0;
        int ch  = q & 3;
        const __half* src = g_W16 + (img * NCHUNK + ch) * (Hn * KCH);
        uint32_t dst = sb + C_B + (uint32_t)(q & 1) * BBUF;
#pragma unroll
        for (int i = 0; i < 8; ++i) {
            int idx = i * NTHREADS + tid;
            int j = idx >> 3, kb = idx & 7;
            cp16(dst + (uint32_t)j * 144u + (uint32_t)kb * 16u, src + idx * 8);
        }
        CP_COMMIT();
    };

    issue_b(0);
    __syncthreads();

    const float scale = __ldg(osc);
    const float dt  = 1.0f / (float)STEPSn;
    const float b30 = __ldg(b3), b31 = __ldg(b3 + 1);

    const int p_mine = tid / TPP;
    const int ksub   = tid % TPP;
    // warp tiling: 2 (M) x 4 (N)
    const int warp_m = wid >> 2;
    const int warp_n = wid & 3;
    const int m0w = warp_m * (PPCT / 2);
    const int n0w = warp_n * 64;
    const int grp = lane >> 2, tig = lane & 3;
    const uint32_t aoff  = (uint32_t)(lane & 15) * 144u + ((uint32_t)(lane >> 4) << 4);
    const uint32_t aoffG = (uint32_t)(lane & 15) * AG_STRIDE + ((uint32_t)(lane >> 4) << 4);
    const uint32_t boff = ((uint32_t)((lane & 7) + ((lane >> 4) << 3))) * 144u
                        + (((uint32_t)(lane >> 3) & 1u) << 4);

    const float* c0s = sf + (SM_C0 >> 2);
    const float* c1s = sf + (SM_C1 >> 2);
    const float* cts = sf + (SM_CT >> 2);
    const float* css = sf + (SM_CS >> 2);
    const float* bas = sf + (SM_BASE >> 2);
    const float* b2s = sf + (SM_B2 >> 2);
    const float* w30s = sf + (SM_W30 >> 2);
    const float* w31s = sf + (SM_W31 >> 2);
    float* part = sf + (C_PART >> 2);

    uint32_t g2a[MI][8], g2b[MI][8];   // layer-2 derivative stash

#pragma unroll 1
    for (int step = 0; step < STEPSn; ++step) {
        const float tcur = dt * (float)step;
        const float px0 = sf[(C_X0 >> 2) + p_mine];
        const float px1 = sf[(C_X1 >> 2) + p_mine];
        const float psv = sf[(C_SS >> 2) + p_mine];

        // layer-1 k-slice for chunk c: batched tanh; h fp16 -> A buf (c&1),
        // g1 fp16 -> full-width AG at final column position.
        auto layer1 = [&](int c) {
            const int kkb = ksub * KPT;
#pragma unroll
            for (int kk2 = 0; kk2 < KPT; kk2 += 4) {
                int kk = kkb + kk2;
                int k = c * KCH + kk;
                float u[4], h[4];
#pragma unroll
                for (int t2 = 0; t2 < 4; ++t2) {
                    int kt = k + t2;
                    u[t2] = bas[kt] + tcur * cts[kt] + psv * css[kt]
                          + px0 * c0s[kt] + px1 * c1s[kt];
                }
                ftanh4(u, h);
                uint32_t o = (uint32_t)(c & 1) * ABUF
                           + (uint32_t)p_mine * 144u + (uint32_t)kk * 2u;
                *reinterpret_cast<__half2*>(smem + C_A + o) =
                    __floats2half2_rn(h[0], h[1]);
                *reinterpret_cast<__half2*>(smem + C_A + o + 4u) =
                    __floats2half2_rn(h[2], h[3]);
                uint32_t og = (uint32_t)p_mine * AG_STRIDE + (uint32_t)k * 2u;
                *reinterpret_cast<__half2*>(smem + C_AG + og) =
                    __floats2half2_rn(1.f - h[0] * h[0], 1.f - h[1] * h[1]);
                *reinterpret_cast<__half2*>(smem + C_AG + og + 4u) =
                    __floats2half2_rn(1.f - h[2] * h[2], 1.f - h[3] * h[3]);
            }
        };

        float acc[MI][8][4];
#pragma unroll
        for (int mi = 0; mi < MI; ++mi)
#pragma unroll
            for (int ni = 0; ni < 8; ++ni)
#pragma unroll
                for (int q = 0; q < 4; ++q) acc[mi][ni][q] = 0.f;

        // ============ pass 0: velocity GEMM (h . W2, single term) ==========
        layer1(0);
#pragma unroll 1
        for (int chunk = 0; chunk < NCHUNK; ++chunk) {
            const int q = step * 8 + chunk;
            CP_WAIT0();
            __syncthreads();
            issue_b(q + 1);

            const uint32_t bb = sb + C_B + (uint32_t)(q & 1) * BBUF;
            const uint32_t ab = sb + C_A + (uint32_t)(chunk & 1) * ABUF;
#pragma unroll
            for (int ks = 0; ks < 4; ++ks) {
                uint32_t a[MI][4];
#pragma unroll
                for (int mi = 0; mi < MI; ++mi) {
                    uint32_t ad = ab + (uint32_t)(m0w + mi * 16) * 144u
                                + (uint32_t)ks * 32u + aoff;
                    ldsm4(a[mi][0], a[mi][1], a[mi][2], a[mi][3], ad);
                }
#pragma unroll
                for (int ng = 0; ng < 4; ++ng) {
                    uint32_t r0, r1, r2, r3;
                    uint32_t bd = bb + (uint32_t)(n0w + ng * 16) * 144u
                                + (uint32_t)ks * 32u + boff;
                    ldsm4(r0, r1, r2, r3, bd);
#pragma unroll
                    for (int mi = 0; mi < MI; ++mi) {
                        mma16816(acc[mi][ng * 2],     a[mi], r0, r1);
                        mma16816(acc[mi][ng * 2 + 1], a[mi], r2, r3);
                    }
                }
            }
            if (chunk + 1 < NCHUNK) layer1(chunk + 1);
        }

        // ---- epilogue 0: h2, v partials; g2 -> registers ----
        {
            float v0p[2 * MI], v1p[2 * MI];
#pragma unroll
            for (int i = 0; i < 2 * MI; ++i) { v0p[i] = 0.f; v1p[i] = 0.f; }
#pragma unroll
            for (int mi = 0; mi < MI; ++mi) {
#pragma unroll
                for (int ni = 0; ni < 8; ++ni) {
                    int j0 = n0w + ni * 8 + tig * 2;
                    float* c = acc[mi][ni];
                    float bj0 = b2s[j0], bj1 = b2s[j0 + 1];
                    float u[4] = {c[0] + bj0, c[1] + bj1, c[2] + bj0, c[3] + bj1};
                    float h[4];
                    ftanh4(u, h);
                    float w300 = w30s[j0], w301 = w30s[j0 + 1];
                    float w310 = w31s[j0], w311 = w31s[j0 + 1];
                    v0p[2*mi]   += w300 * h[0] + w301 * h[1];
                    v0p[2*mi+1] += w300 * h[2] + w301 * h[3];
                    v1p[2*mi]   += w310 * h[0] + w311 * h[1];
                    v1p[2*mi+1] += w310 * h[2] + w311 * h[3];
                    __half2 ga = __floats2half2_rn(1.f - h[0] * h[0], 1.f - h[1] * h[1]);
                    __half2 gb = __floats2half2_rn(1.f - h[2] * h[2], 1.f - h[3] * h[3]);
                    g2a[mi][ni] = *reinterpret_cast<uint32_t*>(&ga);
                    g2b[mi][ni] = *reinterpret_cast<uint32_t*>(&gb);
                }
            }
#pragma unroll
            for (int i = 0; i < 2 * MI; ++i) {
                v0p[i] += __shfl_xor_sync(0xffffffffu, v0p[i], 1);
                v0p[i] += __shfl_xor_sync(0xffffffffu, v0p[i], 2);
                v1p[i] += __shfl_xor_sync(0xffffffffu, v1p[i], 1);
                v1p[i] += __shfl_xor_sync(0xffffffffu, v1p[i], 2);
            }
            if (tig == 0) {
#pragma unroll
                for (int i = 0; i < 2 * MI; ++i) {
                    int p = m0w + (i >> 1) * 16 + grp + (i & 1) * 8;
                    part[0 * 4 * PPCT + warp_n * PPCT + p] = v0p[i];
                    part[1 * 4 * PPCT + warp_n * PPCT + p] = v1p[i];
                }
            }
        }

        // ============ pass 1: divergence GEMM (g1 . M, single term) ========
#pragma unroll
        for (int mi = 0; mi < MI; ++mi)
#pragma unroll
            for (int ni = 0; ni < 8; ++ni)
#pragma unroll
                for (int q = 0; q < 4; ++q) acc[mi][ni][q] = 0.f;

#pragma unroll 1
        for (int chunk = 0; chunk < NCHUNK; ++chunk) {
            const int q = step * 8 + 4 + chunk;
            CP_WAIT0();
            __syncthreads();
            if (q + 1 < NTILES) issue_b(q + 1);

            const uint32_t bb = sb + C_B + (uint32_t)(q & 1) * BBUF;
            const uint32_t ab = sb + C_AG + (uint32_t)chunk * 128u;
#pragma unroll
            for (int ks = 0; ks < 4; ++ks) {
                uint32_t a[MI][4];
#pragma unroll
                for (int mi = 0; mi < MI; ++mi) {
                    uint32_t ad = ab + (uint32_t)(m0w + mi * 16) * AG_STRIDE
                                + (uint32_t)ks * 32u + aoffG;
                    ldsm4(a[mi][0], a[mi][1], a[mi][2], a[mi][3], ad);
                }
#pragma unroll
                for (int ng = 0; ng < 4; ++ng) {
                    uint32_t r0, r1, r2, r3;
                    uint32_t bd = bb + (uint32_t)(n0w + ng * 16) * 144u
                                + (uint32_t)ks * 32u + boff;
                    ldsm4(r0, r1, r2, r3, bd);
#pragma unroll
                    for (int mi = 0; mi < MI; ++mi) {
                        mma16816(acc[mi][ng * 2],     a[mi], r0, r1);
                        mma16816(acc[mi][ng * 2 + 1], a[mi], r2, r3);
                    }
                }
            }
            // no bottom sync: AG read-only; B buffers guarded by top sync
        }

        // ---- epilogue 1: dv partials from g2 registers ----
        {
            float dvp[2 * MI];
#pragma unroll
            for (int i = 0; i < 2 * MI; ++i) dvp[i] = 0.f;
#pragma unroll
            for (int mi = 0; mi < MI; ++mi) {
#pragma unroll
                for (int ni = 0; ni < 8; ++ni) {
                    float* c = acc[mi][ni];
                    float2 ga = __half22float2(
                        *reinterpret_cast<__half2*>(&g2a[mi][ni]));
                    float2 gb = __half22float2(
                        *reinterpret_cast<__half2*>(&g2b[mi][ni]));
                    dvp[2*mi]   += ga.x * c[0] + ga.y * c[1];
                    dvp[2*mi+1] += gb.x * c[2] + gb.y * c[3];
                }
            }
#pragma unroll
            for (int i = 0; i < 2 * MI; ++i) {
                dvp[i] += __shfl_xor_sync(0xffffffffu, dvp[i], 1);
                dvp[i] += __shfl_xor_sync(0xffffffffu, dvp[i], 2);
            }
            if (tig == 0) {
#pragma unroll
                for (int i = 0; i < 2 * MI; ++i) {
                    int p = m0w + (i >> 1) * 16 + grp + (i & 1) * 8;
                    part[2 * 4 * PPCT + warp_n * PPCT + p] = dvp[i];
                }
            }
        }
        __syncthreads();

        // ---- state update ----
        if (tid < PPCT) {
            float v0 = b30, v1 = b31, dv = 0.f;
#pragma unroll
            for (int wn = 0; wn < 4; ++wn) {
                v0 += part[0 * 4 * PPCT + wn * PPCT + tid];
                v1 += part[1 * 4 * PPCT + wn * PPCT + tid];
                dv += part[2 * 4 * PPCT + wn * PPCT + tid];
            }
            sf[(C_X0 >> 2) + tid] += v0 * scale * dt;
            sf[(C_X1 >> 2) + tid] += v1 * scale * dt;
            sf[(C_SS >> 2) + tid] += dv * scale * dt;
        }
        __syncthreads();
    }

    if (tid < PPCT) {
        int gp = gp0 + tid;
        out[gp * 2 + 0] = sf[(C_X0 >> 2) + tid];
        out[gp * 2 + 1] = sf[(C_X1 >> 2) + tid];
        if (out_size >= NPTS * PDn + NPTS)
            out[NPTS * PDn + gp] = sf[(C_SS >> 2) + tid];
    }
}

// SMEM totals per instantiation (must match template constexpr math)
static constexpr int smem_total(int ppct) {
    int c_part = 8192 + 3 * ppct * 4;
    int c_a = (c_part + 12 * ppct * 4 + 127) & ~127;
    int c_b = c_a + 2 * ppct * 144;
    int c_ag = c_b + 2 * 36864;
    return c_ag + ppct * 528;
}

// ---------------------------------------------------------------------------
// kernel_launch
// Inputs (metadata order): x, z, W1, b1, W2, b2, W3, b3, out_scale
// ---------------------------------------------------------------------------
extern "C" void kernel_launch(void* const* d_in, const int* in_sizes, int n_in,
                              void* d_out, int out_size) {
    const float* x   = (const float*)d_in[0];
    const float* z   = (const float*)d_in[1];
    const float* W1  = (const float*)d_in[2];
    const float* b1  = (const float*)d_in[3];
    const float* W2  = (const float*)d_in[4];
    const float* b2  = (const float*)d_in[5];
    const float* W3  = (const float*)d_in[6];
    const float* b3  = (const float*)d_in[7];
    const float* osc = (const float*)d_in[8];
    float* out = (float*)d_out;

    precomp_aux<<<Hn, 128>>>(W1, b1, z);
    precomp_w<<<256, 256>>>(W1, W2, W3);

    const int sm1 = smem_total(128);   // 194048
    const int sm2 = smem_total(64);    // 138752
    cudaFuncSetAttribute(cnf_kernel<128>,
                         cudaFuncAttributeMaxDynamicSharedMemorySize, sm1);
    cudaFuncSetAttribute(cnf_kernel<64>,
                         cudaFuncAttributeMaxDynamicSharedMemorySize, sm2);

    // 3 exact waves of 128-pt CTAs, then a <1-wave tail of 64-pt CTAs.
    cnf_kernel<128><<<NCTA1, NTHREADS, sm1>>>(x, b2, W3, b3, osc, out,
                                              out_size, 0);
    cnf_kernel<64><<<NCTA2, NTHREADS, sm2>>>(x, b2, W3, b3, osc, out,
                                             out_size, PTS1);
}